// round 8
// baseline (speedup 1.0000x reference)
#include <cuda_runtime.h>
#include <cstddef>
#include <cstdint>
#include <math.h>

#define DMODEL 1024
#define NTOK   4096
#define FFDIM  4096
#define SEQ    1024
#define REC_CTAS 128

__device__ float g_xn [NTOK*DMODEL];
__device__ float g_q  [NTOK*DMODEL];
__device__ float g_k  [NTOK*DMODEL];
__device__ float g_v  [NTOK*DMODEL];
__device__ float g_z  [NTOK*DMODEL];
__device__ float g_gm [NTOK*DMODEL];
__device__ float g_t1 [NTOK*128];
__device__ float g_h  [NTOK*DMODEL];
__device__ float g_att[NTOK*DMODEL];
__device__ float g_ao [NTOK*DMODEL];
__device__ float g_y  [NTOK*DMODEL];
__device__ float g_yn [NTOK*DMODEL];
__device__ float g_f1 [NTOK*FFDIM];
__device__ unsigned g_bar_count;
__device__ unsigned g_bar_sense;

// ---------------- small helpers ----------------
__device__ __forceinline__ unsigned f2tf32(float f) {
    unsigned u;
    asm("cvt.rna.tf32.f32 %0, %1;" : "=r"(u) : "f"(f));
    return u;
}

__device__ __forceinline__ void mma_tf32(float* c,
    unsigned a0, unsigned a1, unsigned a2, unsigned a3,
    unsigned b0, unsigned b1)
{
    asm volatile("mma.sync.aligned.m16n8k8.row.col.f32.tf32.tf32.f32 "
                 "{%0,%1,%2,%3}, {%4,%5,%6,%7}, {%8,%9}, {%0,%1,%2,%3};\n"
                 : "+f"(c[0]), "+f"(c[1]), "+f"(c[2]), "+f"(c[3])
                 : "r"(a0), "r"(a1), "r"(a2), "r"(a3), "r"(b0), "r"(b1));
}

__device__ __forceinline__ float multi_reduce32(float (&acc)[32], int lane) {
#pragma unroll
    for (int d = 16; d >= 1; d >>= 1) {
        const bool up = (lane & d) != 0;
#pragma unroll
        for (int i = 0; i < d; i++) {
            float send = up ? acc[i] : acc[i + d];
            float recv = __shfl_xor_sync(0xffffffffu, send, d);
            float keep = up ? acc[i + d] : acc[i];
            acc[i] = keep + recv;
        }
    }
    return acc[0];
}

__device__ __forceinline__ float block_sum256(float v) {
    __shared__ float sred[9];
#pragma unroll
    for (int o = 16; o; o >>= 1) v += __shfl_xor_sync(0xffffffffu, v, o);
    int w = threadIdx.x >> 5, l = threadIdx.x & 31;
    if (l == 0) sred[w] = v;
    __syncthreads();
    if (threadIdx.x < 32) {
        float t = (l < 8) ? sred[l] : 0.f;
#pragma unroll
        for (int o = 4; o; o >>= 1) t += __shfl_xor_sync(0xffffffffu, t, o);
        if (l == 0) sred[8] = t;
    }
    __syncthreads();
    return sred[8];
}

__global__ __launch_bounds__(256)
void rmsnorm_kernel(const float* __restrict__ x, const float* __restrict__ w,
                    float* __restrict__ out) {
    const size_t base = (size_t)blockIdx.x * DMODEL;
    float vb[4]; float ss = 0.f;
#pragma unroll
    for (int i = 0; i < 4; i++) { float t = x[base + threadIdx.x + 256*i]; vb[i] = t; ss += t*t; }
    float inv = 1.f / (sqrtf(block_sum256(ss)) * 0.03125f + 1e-6f);
#pragma unroll
    for (int i = 0; i < 4; i++) { int c = threadIdx.x + 256*i; out[base + c] = w[c] * vb[i] * inv; }
}

__global__ __launch_bounds__(256)
void residual_norm_kernel(const float* __restrict__ x, const float* __restrict__ ao,
                          const float* __restrict__ hs, const float* __restrict__ w,
                          float* __restrict__ y, float* __restrict__ yn) {
    const size_t base = (size_t)blockIdx.x * DMODEL;
    float vb[4]; float ss = 0.f;
#pragma unroll
    for (int i = 0; i < 4; i++) {
        int c = threadIdx.x + 256*i;
        float t = x[base+c] + ao[base+c] + hs[base+c];
        vb[i] = t; y[base+c] = t; ss += t*t;
    }
    float inv = 1.f / (sqrtf(block_sum256(ss)) * 0.03125f + 1e-6f);
#pragma unroll
    for (int i = 0; i < 4; i++) { int c = threadIdx.x + 256*i; yn[base+c] = w[c] * vb[i] * inv; }
}

// ---------------- TF32 tensor-core GEMM ----------------
// C[M,N] = A[M,K] @ B[N,K]^T + bias ; EPI 0=none 1=relu 2=sigmoid+clip 3=gelu ; +res
// Block 128x128, BK=16, 8 warps each on a 64x32 warp tile (4x4 m16n8k8 mmas).
#define TG_BK 16
#define TG_LD 136   // pad 8: frag LDS bank = tq*8+gq -> conflict-free

#define TG_STORE_TILE(buf)                                                        \
    do {                                                                          \
        As[buf][kc+0][lrow]=f2tf32(ra0.x); As[buf][kc+1][lrow]=f2tf32(ra0.y);     \
        As[buf][kc+2][lrow]=f2tf32(ra0.z); As[buf][kc+3][lrow]=f2tf32(ra0.w);     \
        As[buf][kc+4][lrow]=f2tf32(ra1.x); As[buf][kc+5][lrow]=f2tf32(ra1.y);     \
        As[buf][kc+6][lrow]=f2tf32(ra1.z); As[buf][kc+7][lrow]=f2tf32(ra1.w);     \
        Bs[buf][kc+0][lrow]=f2tf32(rb0.x); Bs[buf][kc+1][lrow]=f2tf32(rb0.y);     \
        Bs[buf][kc+2][lrow]=f2tf32(rb0.z); Bs[buf][kc+3][lrow]=f2tf32(rb0.w);     \
        Bs[buf][kc+4][lrow]=f2tf32(rb1.x); Bs[buf][kc+5][lrow]=f2tf32(rb1.y);     \
        Bs[buf][kc+6][lrow]=f2tf32(rb1.z); Bs[buf][kc+7][lrow]=f2tf32(rb1.w);     \
    } while (0)

template<int EPI>
__global__ __launch_bounds__(256, 2)
void tgemm_kernel(const float* __restrict__ A, const float* __restrict__ B,
                  const float* __restrict__ bias, const float* __restrict__ res,
                  float* __restrict__ C, int M, int N, int K)
{
    __shared__ unsigned As[2][TG_BK][TG_LD];
    __shared__ unsigned Bs[2][TG_BK][TG_LD];
    const int tid = threadIdx.x;
    const int wid = tid >> 5, lane = tid & 31;
    const int gq = lane >> 2, tq = lane & 3;
    const int m0 = (wid & 1) * 64, n0 = (wid >> 1) * 32;
    const int bm = blockIdx.y * 128, bn = blockIdx.x * 128;

    const int lrow = tid & 127;            // tile row (m for A, n for B)
    const int kc = (tid >> 7) * 8;         // k sub-chunk within BK

    const float* Ap = A + (size_t)(bm + lrow) * K + kc;
    const float* Bp = B + (size_t)(bn + lrow) * K + kc;

    float acc[4][4][4];
#pragma unroll
    for (int i = 0; i < 4; i++)
#pragma unroll
        for (int j = 0; j < 4; j++)
#pragma unroll
            for (int e = 0; e < 4; e++) acc[i][j][e] = 0.f;

    float4 ra0 = *(const float4*)(Ap);
    float4 ra1 = *(const float4*)(Ap + 4);
    float4 rb0 = *(const float4*)(Bp);
    float4 rb1 = *(const float4*)(Bp + 4);
    TG_STORE_TILE(0);
    __syncthreads();

    int buf = 0;
    for (int kt = 0; kt < K; kt += TG_BK) {
        const bool more = (kt + TG_BK) < K;
        if (more) {
            ra0 = *(const float4*)(Ap + kt + TG_BK);
            ra1 = *(const float4*)(Ap + kt + TG_BK + 4);
            rb0 = *(const float4*)(Bp + kt + TG_BK);
            rb1 = *(const float4*)(Bp + kt + TG_BK + 4);
        }
#pragma unroll
        for (int kb = 0; kb < TG_BK; kb += 8) {
            unsigned af[4][4], bf[4][2];
#pragma unroll
            for (int i = 0; i < 4; i++) {
                const int r = m0 + i*16 + gq;
                af[i][0] = As[buf][kb+tq  ][r  ];
                af[i][1] = As[buf][kb+tq  ][r+8];
                af[i][2] = As[buf][kb+tq+4][r  ];
                af[i][3] = As[buf][kb+tq+4][r+8];
            }
#pragma unroll
            for (int j = 0; j < 4; j++) {
                const int n = n0 + j*8 + gq;
                bf[j][0] = Bs[buf][kb+tq  ][n];
                bf[j][1] = Bs[buf][kb+tq+4][n];
            }
#pragma unroll
            for (int i = 0; i < 4; i++)
#pragma unroll
                for (int j = 0; j < 4; j++)
                    mma_tf32(acc[i][j], af[i][0], af[i][1], af[i][2], af[i][3],
                             bf[j][0], bf[j][1]);
        }
        if (more) {
            __syncthreads();
            TG_STORE_TILE(buf ^ 1);
            __syncthreads();
            buf ^= 1;
        }
    }

#pragma unroll
    for (int i = 0; i < 4; i++) {
#pragma unroll
        for (int half = 0; half < 2; half++) {
            const int gr = bm + m0 + i*16 + gq + half*8;
            float* crow = C + (size_t)gr * N;
            const float* rrow = res ? res + (size_t)gr * N : nullptr;
#pragma unroll
            for (int j = 0; j < 4; j++) {
                const int gc = bn + n0 + j*8 + tq*2;
#pragma unroll
                for (int e = 0; e < 2; e++) {
                    float vv = acc[i][j][half*2 + e] + bias[gc + e];
                    if (EPI == 1) vv = fmaxf(vv, 0.f);
                    else if (EPI == 2) {
                        vv = 1.f / (1.f + __expf(-vv));
                        vv = fminf(fmaxf(vv, 1e-6f), 1.f - 1e-6f);
                    } else if (EPI == 3) {
                        float u = 0.7978845608028654f * (vv + 0.044715f * vv * vv * vv);
                        vv = 0.5f * vv * (1.f + tanhf(u));
                    }
                    if (rrow) vv += rrow[gc + e];
                    crow[gc + e] = vv;
                }
            }
        }
    }
}

// ---------------- persistent recurrence (unchanged, known-good) ----------------
__global__ __launch_bounds__(256, 1)
void recurrence_kernel(const float* __restrict__ z, const float* __restrict__ gm,
                       const float* __restrict__ Wg, const float* __restrict__ bg,
                       float* __restrict__ hs)
{
    const int tid = threadIdx.x, w = tid >> 5, l = tid & 31;
    const int blk = blockIdx.x;
    const int k0 = w * 128 + l * 4;
    float4 wv[8];
#pragma unroll
    for (int r = 0; r < 8; r++)
        wv[r] = *(const float4*)(Wg + (size_t)(blk*8 + r) * DMODEL + k0);

    __shared__ float red[256];
    float bgv = 0.f, hprev = 0.f; int jout = 0, bout = 0;
    if (tid < 32) { jout = blk*8 + (tid >> 2); bout = tid & 3; bgv = bg[jout]; }

    for (int t = 0; t < SEQ; t++) {
        float acc[32];
#pragma unroll
        for (int a = 0; a < 32; a++) acc[a] = 0.f;
        if (t > 0) {
#pragma unroll
            for (int b = 0; b < 4; b++) {
                float4 hv = __ldcg((const float4*)(hs + ((size_t)b*SEQ + (t-1))*DMODEL + k0));
#pragma unroll
                for (int r = 0; r < 8; r++) {
                    acc[r*4+b] = fmaf(wv[r].x, hv.x, acc[r*4+b]);
                    acc[r*4+b] = fmaf(wv[r].y, hv.y, acc[r*4+b]);
                    acc[r*4+b] = fmaf(wv[r].z, hv.z, acc[r*4+b]);
                    acc[r*4+b] = fmaf(wv[r].w, hv.w, acc[r*4+b]);
                }
            }
        }
        float part = multi_reduce32(acc, l);
        red[w*32 + l] = part;
        __syncthreads();
        if (tid < 32) {
            float sum = bgv;
#pragma unroll
            for (int ww = 0; ww < 8; ww++) sum += red[ww*32 + tid];
            float sig = 1.f / (1.f + __expf(-sum));
            size_t base = ((size_t)bout * SEQ + t) * DMODEL + jout;
            hprev = z[base] * sig + gm[base] * hprev;
            hs[base] = hprev;
            __threadfence();
        }
        __syncthreads();
        if (tid == 0) {
            unsigned sv = *(volatile unsigned*)&g_bar_sense;
            unsigned prev = atomicAdd(&g_bar_count, 1u);
            if (prev == REC_CTAS - 1) {
                g_bar_count = 0;
                __threadfence();
                atomicExch(&g_bar_sense, sv ^ 1u);
            } else {
                while (*(volatile unsigned*)&g_bar_sense == sv) { }
            }
            __threadfence();
        }
        __syncthreads();
    }
}

// ---------------- fused attention (PV via smem p: low regs, no butterfly) -----
__global__ __launch_bounds__(256)
void attn_kernel(const float* __restrict__ q, const float* __restrict__ k,
                 const float* __restrict__ v, float* __restrict__ ao)
{
    const int qb = blockIdx.x & 127;
    const int bh = blockIdx.x >> 7;
    const int b = bh >> 4, h = bh & 15;
    __shared__ float Qs[8][64];
    __shared__ float Ts[64*65];
    __shared__ float ps[8][64];
    const int tid = threadIdx.x, w = tid >> 5, l = tid & 31;
    const size_t bbase = (size_t)b * SEQ * DMODEL + (size_t)h * 64;
    const int qrow0 = qb * 8;

    for (int idx = tid; idx < 8*64; idx += 256)
        Qs[idx>>6][idx&63] = q[bbase + (size_t)(qrow0 + (idx>>6)) * DMODEL + (idx&63)];

    float p[32];
#pragma unroll 1
    for (int j = 0; j < 16; j++) {
        __syncthreads();
        for (int idx = tid; idx < 64*64; idx += 256)
            Ts[(idx>>6)*65 + (idx&63)] = k[bbase + (size_t)(j*64 + (idx>>6)) * DMODEL + (idx&63)];
        __syncthreads();
#pragma unroll
        for (int ii = 0; ii < 2; ii++) {
            const int kr = l + 32*ii;
            float s = 0.f;
#pragma unroll
            for (int d = 0; d < 64; d++) s = fmaf(Qs[w][d], Ts[kr*65 + d], s);
            p[2*j + ii] = s * 0.125f;
        }
    }
    float m = -3.0e38f;
#pragma unroll
    for (int i = 0; i < 32; i++) m = fmaxf(m, p[i]);
#pragma unroll
    for (int o = 16; o; o >>= 1) m = fmaxf(m, __shfl_xor_sync(0xffffffffu, m, o));
    float s = 0.f;
#pragma unroll
    for (int i = 0; i < 32; i++) { p[i] = __expf(p[i] - m); s += p[i]; }
#pragma unroll
    for (int o = 16; o; o >>= 1) s += __shfl_xor_sync(0xffffffffu, s, o);
    float inv = 1.f / s;
#pragma unroll
    for (int i = 0; i < 32; i++) p[i] *= inv;

    float o0 = 0.f, o1 = 0.f;   // lane's two output dims: l and 32+l
#pragma unroll 1
    for (int j = 0; j < 16; j++) {
        __syncthreads();
        for (int idx = tid; idx < 64*64; idx += 256)
            Ts[(idx>>6)*65 + (idx&63)] = v[bbase + (size_t)(j*64 + (idx>>6)) * DMODEL + (idx&63)];
        ps[w][l]      = p[2*j];       // k row j*64 + l
        ps[w][32 + l] = p[2*j + 1];   // k row j*64 + 32 + l
        __syncthreads();
#pragma unroll
        for (int kk = 0; kk < 64; kk++) {
            const float pv = ps[w][kk];
            o0 = fmaf(pv, Ts[kk*65 + l],      o0);
            o1 = fmaf(pv, Ts[kk*65 + 32 + l], o1);
        }
    }
    size_t ob = bbase + (size_t)(qrow0 + w) * DMODEL;
    ao[ob + l]      = o0;
    ao[ob + 32 + l] = o1;
}

extern "C" void kernel_launch(void* const* d_in, const int* in_sizes, int n_in,
                              void* d_out, int out_size)
{
    (void)in_sizes; (void)n_in; (void)out_size;
    const float* x   = (const float*)d_in[0];
    const float* n1w = (const float*)d_in[1];
    const float* Wq  = (const float*)d_in[2];  const float* bq = (const float*)d_in[3];
    const float* Wk  = (const float*)d_in[4];  const float* bk = (const float*)d_in[5];
    const float* Wv  = (const float*)d_in[6];  const float* bv = (const float*)d_in[7];
    const float* Wz  = (const float*)d_in[8];  const float* bz = (const float*)d_in[9];
    const float* Wg  = (const float*)d_in[10]; const float* bg = (const float*)d_in[11];
    const float* gdw = (const float*)d_in[12]; const float* gdb= (const float*)d_in[13];
    const float* guw = (const float*)d_in[14]; const float* gub= (const float*)d_in[15];
    const float* Wo  = (const float*)d_in[16]; const float* bo = (const float*)d_in[17];
    const float* n2w = (const float*)d_in[18];
    const float* f1w = (const float*)d_in[19]; const float* f1b= (const float*)d_in[20];
    const float* f2w = (const float*)d_in[21]; const float* f2b= (const float*)d_in[22];
    float* out = (float*)d_out;

    float *xn, *qp, *kp, *vp, *zp, *gmp, *t1, *hp, *attp, *aop, *yp, *ynp, *f1p;
    cudaGetSymbolAddress((void**)&xn,  g_xn);
    cudaGetSymbolAddress((void**)&qp,  g_q);
    cudaGetSymbolAddress((void**)&kp,  g_k);
    cudaGetSymbolAddress((void**)&vp,  g_v);
    cudaGetSymbolAddress((void**)&zp,  g_z);
    cudaGetSymbolAddress((void**)&gmp, g_gm);
    cudaGetSymbolAddress((void**)&t1,  g_t1);
    cudaGetSymbolAddress((void**)&hp,  g_h);
    cudaGetSymbolAddress((void**)&attp,g_att);
    cudaGetSymbolAddress((void**)&aop, g_ao);
    cudaGetSymbolAddress((void**)&yp,  g_y);
    cudaGetSymbolAddress((void**)&ynp, g_yn);
    cudaGetSymbolAddress((void**)&f1p, g_f1);

    // 1. rmsnorm
    rmsnorm_kernel<<<NTOK, 256>>>(x, n1w, xn);
    // 2. Q/K/V/Z projections (TF32 tensor cores)
    dim3 gDD(DMODEL/128, NTOK/128);
    tgemm_kernel<0><<<gDD, 256>>>(xn, Wq, bq, nullptr, qp, NTOK, DMODEL, DMODEL);
    tgemm_kernel<0><<<gDD, 256>>>(xn, Wk, bk, nullptr, kp, NTOK, DMODEL, DMODEL);
    tgemm_kernel<0><<<gDD, 256>>>(xn, Wv, bv, nullptr, vp, NTOK, DMODEL, DMODEL);
    tgemm_kernel<0><<<gDD, 256>>>(xn, Wz, bz, nullptr, zp, NTOK, DMODEL, DMODEL);
    // 3. gamma = clip(sigmoid(relu(z@gdw^T+gdb)@guw^T+gub))
    tgemm_kernel<1><<<dim3(1, NTOK/128), 256>>>(zp, gdw, gdb, nullptr, t1, NTOK, 128, DMODEL);
    tgemm_kernel<2><<<gDD, 256>>>(t1, guw, gub, nullptr, gmp, NTOK, DMODEL, 128);
    // 4. recurrence (persistent grid)
    recurrence_kernel<<<REC_CTAS, 256>>>(zp, gmp, Wg, bg, hp);
    // 5. attention + Wo
    attn_kernel<<<4*16*128, 256>>>(qp, kp, vp, attp);
    tgemm_kernel<0><<<gDD, 256>>>(attp, Wo, bo, nullptr, aop, NTOK, DMODEL, DMODEL);
    // 6-7. residual + norm2, FFN, final residual (-> d_out)
    residual_norm_kernel<<<NTOK, 256>>>(x, aop, hp, n2w, yp, ynp);
    tgemm_kernel<3><<<dim3(FFDIM/128, NTOK/128), 256>>>(ynp, f1w, f1b, nullptr, f1p, NTOK, FFDIM, DMODEL);
    tgemm_kernel<0><<<gDD, 256>>>(f1p, f2w, f2b, yp, out, NTOK, DMODEL, FFDIM);
}

// round 9
// speedup vs baseline: 1.4669x; 1.4669x over previous
#include <cuda_runtime.h>
#include <cstddef>
#include <cstdint>
#include <math.h>

#define DMODEL 1024
#define NTOK   4096
#define FFDIM  4096
#define SEQ    1024
#define REC_CTAS 128

__device__ float g_xn [NTOK*DMODEL];
__device__ float g_q  [NTOK*DMODEL];
__device__ float g_k  [NTOK*DMODEL];
__device__ float g_v  [NTOK*DMODEL];
__device__ float g_z  [NTOK*DMODEL];
__device__ float g_gm [NTOK*DMODEL];
__device__ float g_t1 [NTOK*128];
__device__ float g_h  [NTOK*DMODEL];
__device__ float g_att[NTOK*DMODEL];
__device__ float g_ao [NTOK*DMODEL];
__device__ float g_y  [NTOK*DMODEL];
__device__ float g_yn [NTOK*DMODEL];
__device__ float g_f1 [NTOK*FFDIM];
__device__ unsigned g_bar_count;
__device__ unsigned g_bar_sense;

// ---------------- helpers ----------------
__device__ __forceinline__ unsigned f2tf32(float f) {
    unsigned u;
    asm("cvt.rna.tf32.f32 %0, %1;" : "=r"(u) : "f"(f));
    return u;
}

__device__ __forceinline__ void mma_tf32(float* c,
    unsigned a0, unsigned a1, unsigned a2, unsigned a3,
    unsigned b0, unsigned b1)
{
    asm volatile("mma.sync.aligned.m16n8k8.row.col.f32.tf32.tf32.f32 "
                 "{%0,%1,%2,%3}, {%4,%5,%6,%7}, {%8,%9}, {%0,%1,%2,%3};\n"
                 : "+f"(c[0]), "+f"(c[1]), "+f"(c[2]), "+f"(c[3])
                 : "r"(a0), "r"(a1), "r"(a2), "r"(a3), "r"(b0), "r"(b1));
}

__device__ __forceinline__ float multi_reduce32(float (&acc)[32], int lane) {
#pragma unroll
    for (int d = 16; d >= 1; d >>= 1) {
        const bool up = (lane & d) != 0;
#pragma unroll
        for (int i = 0; i < d; i++) {
            float send = up ? acc[i] : acc[i + d];
            float recv = __shfl_xor_sync(0xffffffffu, send, d);
            float keep = up ? acc[i + d] : acc[i];
            acc[i] = keep + recv;
        }
    }
    return acc[0];
}

__device__ __forceinline__ float block_sum256(float v) {
    __shared__ float sred[9];
#pragma unroll
    for (int o = 16; o; o >>= 1) v += __shfl_xor_sync(0xffffffffu, v, o);
    int w = threadIdx.x >> 5, l = threadIdx.x & 31;
    if (l == 0) sred[w] = v;
    __syncthreads();
    if (threadIdx.x < 32) {
        float t = (l < 8) ? sred[l] : 0.f;
#pragma unroll
        for (int o = 4; o; o >>= 1) t += __shfl_xor_sync(0xffffffffu, t, o);
        if (l == 0) sred[8] = t;
    }
    __syncthreads();
    return sred[8];
}

__global__ __launch_bounds__(256)
void rmsnorm_kernel(const float* __restrict__ x, const float* __restrict__ w,
                    float* __restrict__ out) {
    const size_t base = (size_t)blockIdx.x * DMODEL;
    float vb[4]; float ss = 0.f;
#pragma unroll
    for (int i = 0; i < 4; i++) { float t = x[base + threadIdx.x + 256*i]; vb[i] = t; ss += t*t; }
    float inv = 1.f / (sqrtf(block_sum256(ss)) * 0.03125f + 1e-6f);
#pragma unroll
    for (int i = 0; i < 4; i++) { int c = threadIdx.x + 256*i; out[base + c] = w[c] * vb[i] * inv; }
}

__global__ __launch_bounds__(256)
void residual_norm_kernel(const float* __restrict__ x, const float* __restrict__ ao,
                          const float* __restrict__ hs, const float* __restrict__ w,
                          float* __restrict__ y, float* __restrict__ yn) {
    const size_t base = (size_t)blockIdx.x * DMODEL;
    float vb[4]; float ss = 0.f;
#pragma unroll
    for (int i = 0; i < 4; i++) {
        int c = threadIdx.x + 256*i;
        float t = x[base+c] + ao[base+c] + hs[base+c];
        vb[i] = t; y[base+c] = t; ss += t*t;
    }
    float inv = 1.f / (sqrtf(block_sum256(ss)) * 0.03125f + 1e-6f);
#pragma unroll
    for (int i = 0; i < 4; i++) { int c = threadIdx.x + 256*i; yn[base+c] = w[c] * vb[i] * inv; }
}

// ---------------- TF32 tensor-core GEMM body ----------------
// C[M,N] = A[M,K] @ B[N,K]^T + bias ; single __syncthreads per k-tile.
#define TG_BK 16
#define TG_LD 136

#define TG_STORE_TILE(buf)                                                        \
    do {                                                                          \
        As[buf][kc+0][lrow]=f2tf32(ra0.x); As[buf][kc+1][lrow]=f2tf32(ra0.y);     \
        As[buf][kc+2][lrow]=f2tf32(ra0.z); As[buf][kc+3][lrow]=f2tf32(ra0.w);     \
        As[buf][kc+4][lrow]=f2tf32(ra1.x); As[buf][kc+5][lrow]=f2tf32(ra1.y);     \
        As[buf][kc+6][lrow]=f2tf32(ra1.z); As[buf][kc+7][lrow]=f2tf32(ra1.w);     \
        Bs[buf][kc+0][lrow]=f2tf32(rb0.x); Bs[buf][kc+1][lrow]=f2tf32(rb0.y);     \
        Bs[buf][kc+2][lrow]=f2tf32(rb0.z); Bs[buf][kc+3][lrow]=f2tf32(rb0.w);     \
        Bs[buf][kc+4][lrow]=f2tf32(rb1.x); Bs[buf][kc+5][lrow]=f2tf32(rb1.y);     \
        Bs[buf][kc+6][lrow]=f2tf32(rb1.z); Bs[buf][kc+7][lrow]=f2tf32(rb1.w);     \
    } while (0)

template<int EPI>
__device__ __forceinline__
void tgemm_body(const float* __restrict__ A, const float* __restrict__ B,
                const float* __restrict__ bias, const float* __restrict__ res,
                float* __restrict__ C, int N, int K,
                unsigned (*As)[TG_BK][TG_LD], unsigned (*Bs)[TG_BK][TG_LD],
                int bm, int bn)
{
    const int tid = threadIdx.x;
    const int wid = tid >> 5, lane = tid & 31;
    const int gq = lane >> 2, tq = lane & 3;
    const int m0 = (wid & 1) * 64, n0 = (wid >> 1) * 32;

    const int lrow = tid & 127;
    const int kc = (tid >> 7) * 8;

    const float* Ap = A + (size_t)(bm + lrow) * K + kc;
    const float* Bp = B + (size_t)(bn + lrow) * K + kc;

    float acc[4][4][4];
#pragma unroll
    for (int i = 0; i < 4; i++)
#pragma unroll
        for (int j = 0; j < 4; j++)
#pragma unroll
            for (int e = 0; e < 4; e++) acc[i][j][e] = 0.f;

    float4 ra0 = *(const float4*)(Ap);
    float4 ra1 = *(const float4*)(Ap + 4);
    float4 rb0 = *(const float4*)(Bp);
    float4 rb1 = *(const float4*)(Bp + 4);
    TG_STORE_TILE(0);
    __syncthreads();

    int buf = 0;
    for (int kt = 0; kt < K; kt += TG_BK) {
        const bool more = (kt + TG_BK) < K;
        if (more) {
            ra0 = *(const float4*)(Ap + kt + TG_BK);
            ra1 = *(const float4*)(Ap + kt + TG_BK + 4);
            rb0 = *(const float4*)(Bp + kt + TG_BK);
            rb1 = *(const float4*)(Bp + kt + TG_BK + 4);
        }
#pragma unroll
        for (int kb = 0; kb < TG_BK; kb += 8) {
            unsigned bf[4][2];
#pragma unroll
            for (int j = 0; j < 4; j++) {
                const int n = n0 + j*8 + gq;
                bf[j][0] = Bs[buf][kb+tq  ][n];
                bf[j][1] = Bs[buf][kb+tq+4][n];
            }
#pragma unroll
            for (int i = 0; i < 4; i++) {
                const int r = m0 + i*16 + gq;
                unsigned a0 = As[buf][kb+tq  ][r  ];
                unsigned a1 = As[buf][kb+tq  ][r+8];
                unsigned a2 = As[buf][kb+tq+4][r  ];
                unsigned a3 = As[buf][kb+tq+4][r+8];
#pragma unroll
                for (int j = 0; j < 4; j++)
                    mma_tf32(acc[i][j], a0, a1, a2, a3, bf[j][0], bf[j][1]);
            }
        }
        if (more) {
            TG_STORE_TILE(buf ^ 1);   // buf^1 was fully consumed before last sync
            __syncthreads();          // single barrier per tile
            buf ^= 1;
        }
    }

#pragma unroll
    for (int i = 0; i < 4; i++) {
#pragma unroll
        for (int half = 0; half < 2; half++) {
            const int gr = bm + m0 + i*16 + gq + half*8;
            float* crow = C + (size_t)gr * N;
            const float* rrow = res ? res + (size_t)gr * N : nullptr;
#pragma unroll
            for (int j = 0; j < 4; j++) {
                const int gc = bn + n0 + j*8 + tq*2;
#pragma unroll
                for (int e = 0; e < 2; e++) {
                    float vv = acc[i][j][half*2 + e] + bias[gc + e];
                    if (EPI == 1) vv = fmaxf(vv, 0.f);
                    else if (EPI == 2) {
                        vv = 1.f / (1.f + __expf(-vv));
                        vv = fminf(fmaxf(vv, 1e-6f), 1.f - 1e-6f);
                    } else if (EPI == 3) {
                        float u = 0.7978845608028654f * (vv + 0.044715f * vv * vv * vv);
                        vv = 0.5f * vv * (1.f + tanhf(u));
                    }
                    if (rrow) vv += rrow[gc + e];
                    crow[gc + e] = vv;
                }
            }
        }
    }
}

template<int EPI>
__global__ __launch_bounds__(256, 2)
void tgemm_kernel(const float* __restrict__ A, const float* __restrict__ B,
                  const float* __restrict__ bias, const float* __restrict__ res,
                  float* __restrict__ C, int M, int N, int K)
{
    __shared__ unsigned As[2][TG_BK][TG_LD];
    __shared__ unsigned Bs[2][TG_BK][TG_LD];
    tgemm_body<EPI>(A, B, bias, res, C, N, K, As, Bs,
                    blockIdx.y * 128, blockIdx.x * 128);
}

// Fused Q/K/V/Z: blockIdx.z selects weight/bias/output triple.
struct Ptr3 { const float* B; const float* bias; float* C; };
struct Quad { Ptr3 p[4]; };

__global__ __launch_bounds__(256, 2)
void tgemm4_kernel(const float* __restrict__ A, Quad q, int N, int K)
{
    __shared__ unsigned As[2][TG_BK][TG_LD];
    __shared__ unsigned Bs[2][TG_BK][TG_LD];
    Ptr3 pr = q.p[blockIdx.z];
    tgemm_body<0>(A, pr.B, pr.bias, nullptr, pr.C, N, K, As, Bs,
                  blockIdx.y * 128, blockIdx.x * 128);
}

// ---------------- persistent recurrence (known-good) ----------------
__global__ __launch_bounds__(256, 1)
void recurrence_kernel(const float* __restrict__ z, const float* __restrict__ gm,
                       const float* __restrict__ Wg, const float* __restrict__ bg,
                       float* __restrict__ hs)
{
    const int tid = threadIdx.x, w = tid >> 5, l = tid & 31;
    const int blk = blockIdx.x;
    const int k0 = w * 128 + l * 4;
    float4 wv[8];
#pragma unroll
    for (int r = 0; r < 8; r++)
        wv[r] = *(const float4*)(Wg + (size_t)(blk*8 + r) * DMODEL + k0);

    __shared__ float red[256];
    float bgv = 0.f, hprev = 0.f; int jout = 0, bout = 0;
    if (tid < 32) { jout = blk*8 + (tid >> 2); bout = tid & 3; bgv = bg[jout]; }

    for (int t = 0; t < SEQ; t++) {
        float acc[32];
#pragma unroll
        for (int a = 0; a < 32; a++) acc[a] = 0.f;
        if (t > 0) {
#pragma unroll
            for (int b = 0; b < 4; b++) {
                float4 hv = __ldcg((const float4*)(hs + ((size_t)b*SEQ + (t-1))*DMODEL + k0));
#pragma unroll
                for (int r = 0; r < 8; r++) {
                    acc[r*4+b] = fmaf(wv[r].x, hv.x, acc[r*4+b]);
                    acc[r*4+b] = fmaf(wv[r].y, hv.y, acc[r*4+b]);
                    acc[r*4+b] = fmaf(wv[r].z, hv.z, acc[r*4+b]);
                    acc[r*4+b] = fmaf(wv[r].w, hv.w, acc[r*4+b]);
                }
            }
        }
        float part = multi_reduce32(acc, l);
        red[w*32 + l] = part;
        __syncthreads();
        if (tid < 32) {
            float sum = bgv;
#pragma unroll
            for (int ww = 0; ww < 8; ww++) sum += red[ww*32 + tid];
            float sig = 1.f / (1.f + __expf(-sum));
            size_t base = ((size_t)bout * SEQ + t) * DMODEL + jout;
            hprev = z[base] * sig + gm[base] * hprev;
            hs[base] = hprev;
            __threadfence();
        }
        __syncthreads();
        if (tid == 0) {
            unsigned sv = *(volatile unsigned*)&g_bar_sense;
            unsigned prev = atomicAdd(&g_bar_count, 1u);
            if (prev == REC_CTAS - 1) {
                g_bar_count = 0;
                __threadfence();
                atomicExch(&g_bar_sense, sv ^ 1u);
            } else {
                while (*(volatile unsigned*)&g_bar_sense == sv) { }
            }
            __threadfence();
        }
        __syncthreads();
    }
}

// ---------------- fused attention (R6 butterfly version — measured good) -----
__global__ __launch_bounds__(256)
void attn_kernel(const float* __restrict__ q, const float* __restrict__ k,
                 const float* __restrict__ v, float* __restrict__ ao)
{
    const int qb = blockIdx.x & 127;
    const int bh = blockIdx.x >> 7;
    const int b = bh >> 4, h = bh & 15;
    __shared__ float Qs[8][64];
    __shared__ float Ts[64*65];
    const int tid = threadIdx.x, w = tid >> 5, l = tid & 31;
    const size_t bbase = (size_t)b * SEQ * DMODEL + (size_t)h * 64;
    const int qrow0 = qb * 8;

    for (int idx = tid; idx < 8*64; idx += 256)
        Qs[idx>>6][idx&63] = q[bbase + (size_t)(qrow0 + (idx>>6)) * DMODEL + (idx&63)];

    float p[32];
#pragma unroll 1
    for (int j = 0; j < 16; j++) {
        __syncthreads();
        for (int idx = tid; idx < 64*64; idx += 256)
            Ts[(idx>>6)*65 + (idx&63)] = k[bbase + (size_t)(j*64 + (idx>>6)) * DMODEL + (idx&63)];
        __syncthreads();
#pragma unroll
        for (int ii = 0; ii < 2; ii++) {
            const int kr = l + 32*ii;
            float s = 0.f;
#pragma unroll
            for (int d = 0; d < 64; d++) s = fmaf(Qs[w][d], Ts[kr*65 + d], s);
            p[2*j + ii] = s * 0.125f;
        }
    }
    float m = -3.0e38f;
#pragma unroll
    for (int i = 0; i < 32; i++) m = fmaxf(m, p[i]);
#pragma unroll
    for (int o = 16; o; o >>= 1) m = fmaxf(m, __shfl_xor_sync(0xffffffffu, m, o));
    float s = 0.f;
#pragma unroll
    for (int i = 0; i < 32; i++) { p[i] = __expf(p[i] - m); s += p[i]; }
#pragma unroll
    for (int o = 16; o; o >>= 1) s += __shfl_xor_sync(0xffffffffu, s, o);
    float inv = 1.f / s;
#pragma unroll
    for (int i = 0; i < 32; i++) p[i] *= inv;

    float o0[32], o1[32];
#pragma unroll
    for (int i = 0; i < 32; i++) { o0[i] = 0.f; o1[i] = 0.f; }
#pragma unroll 1
    for (int j = 0; j < 16; j++) {
        __syncthreads();
        for (int idx = tid; idx < 64*64; idx += 256)
            Ts[(idx>>6)*65 + (idx&63)] = v[bbase + (size_t)(j*64 + (idx>>6)) * DMODEL + (idx&63)];
        __syncthreads();
#pragma unroll
        for (int ii = 0; ii < 2; ii++) {
            const int kr = l + 32*ii;
            const float pi = p[2*j + ii];
#pragma unroll
            for (int d = 0; d < 32; d++) o0[d] = fmaf(pi, Ts[kr*65 + d],      o0[d]);
#pragma unroll
            for (int d = 0; d < 32; d++) o1[d] = fmaf(pi, Ts[kr*65 + 32 + d], o1[d]);
        }
    }
    float r0 = multi_reduce32(o0, l);
    float r1 = multi_reduce32(o1, l);
    size_t ob = bbase + (size_t)(qrow0 + w) * DMODEL;
    ao[ob + l] = r0;
    ao[ob + 32 + l] = r1;
}

extern "C" void kernel_launch(void* const* d_in, const int* in_sizes, int n_in,
                              void* d_out, int out_size)
{
    (void)in_sizes; (void)n_in; (void)out_size;
    const float* x   = (const float*)d_in[0];
    const float* n1w = (const float*)d_in[1];
    const float* Wq  = (const float*)d_in[2];  const float* bq = (const float*)d_in[3];
    const float* Wk  = (const float*)d_in[4];  const float* bk = (const float*)d_in[5];
    const float* Wv  = (const float*)d_in[6];  const float* bv = (const float*)d_in[7];
    const float* Wz  = (const float*)d_in[8];  const float* bz = (const float*)d_in[9];
    const float* Wg  = (const float*)d_in[10]; const float* bg = (const float*)d_in[11];
    const float* gdw = (const float*)d_in[12]; const float* gdb= (const float*)d_in[13];
    const float* guw = (const float*)d_in[14]; const float* gub= (const float*)d_in[15];
    const float* Wo  = (const float*)d_in[16]; const float* bo = (const float*)d_in[17];
    const float* n2w = (const float*)d_in[18];
    const float* f1w = (const float*)d_in[19]; const float* f1b= (const float*)d_in[20];
    const float* f2w = (const float*)d_in[21]; const float* f2b= (const float*)d_in[22];
    float* out = (float*)d_out;

    float *xn, *qp, *kp, *vp, *zp, *gmp, *t1, *hp, *attp, *aop, *yp, *ynp, *f1p;
    cudaGetSymbolAddress((void**)&xn,  g_xn);
    cudaGetSymbolAddress((void**)&qp,  g_q);
    cudaGetSymbolAddress((void**)&kp,  g_k);
    cudaGetSymbolAddress((void**)&vp,  g_v);
    cudaGetSymbolAddress((void**)&zp,  g_z);
    cudaGetSymbolAddress((void**)&gmp, g_gm);
    cudaGetSymbolAddress((void**)&t1,  g_t1);
    cudaGetSymbolAddress((void**)&hp,  g_h);
    cudaGetSymbolAddress((void**)&attp,g_att);
    cudaGetSymbolAddress((void**)&aop, g_ao);
    cudaGetSymbolAddress((void**)&yp,  g_y);
    cudaGetSymbolAddress((void**)&ynp, g_yn);
    cudaGetSymbolAddress((void**)&f1p, g_f1);

    // 1. rmsnorm
    rmsnorm_kernel<<<NTOK, 256>>>(x, n1w, xn);
    // 2. Q/K/V/Z projections fused into one launch (grid.z selects weights)
    Quad quad;
    quad.p[0] = {Wq, bq, qp};
    quad.p[1] = {Wk, bk, kp};
    quad.p[2] = {Wv, bv, vp};
    quad.p[3] = {Wz, bz, zp};
    tgemm4_kernel<<<dim3(DMODEL/128, NTOK/128, 4), 256>>>(xn, quad, DMODEL, DMODEL);
    // 3. gamma = clip(sigmoid(relu(z@gdw^T+gdb)@guw^T+gub))
    tgemm_kernel<1><<<dim3(1, NTOK/128), 256>>>(zp, gdw, gdb, nullptr, t1, NTOK, 128, DMODEL);
    tgemm_kernel<2><<<dim3(DMODEL/128, NTOK/128), 256>>>(t1, guw, gub, nullptr, gmp, NTOK, DMODEL, 128);
    // 4. recurrence (persistent grid)
    recurrence_kernel<<<REC_CTAS, 256>>>(zp, gmp, Wg, bg, hp);
    // 5. attention + Wo
    attn_kernel<<<4*16*128, 256>>>(qp, kp, vp, attp);
    tgemm_kernel<0><<<dim3(DMODEL/128, NTOK/128), 256>>>(attp, Wo, bo, nullptr, aop, NTOK, DMODEL, DMODEL);
    // 6-7. residual + norm2, FFN, final residual (-> d_out)
    residual_norm_kernel<<<NTOK, 256>>>(x, aop, hp, n2w, yp, ynp);
    tgemm_kernel<3><<<dim3(FFDIM/128, NTOK/128), 256>>>(ynp, f1w, f1b, nullptr, f1p, NTOK, FFDIM, DMODEL);
    tgemm_kernel<0><<<dim3(DMODEL/128, NTOK/128), 256>>>(f1p, f2w, f2b, yp, out, NTOK, DMODEL, FFDIM);
}

// round 10
// speedup vs baseline: 1.7793x; 1.2130x over previous
#include <cuda_runtime.h>
#include <cstddef>
#include <cstdint>
#include <math.h>

#define DMODEL 1024
#define NTOK   4096
#define FFDIM  4096
#define SEQ    1024
#define REC_CTAS 128

__device__ float g_xn [NTOK*DMODEL];
__device__ float g_q  [NTOK*DMODEL];
__device__ float g_k  [NTOK*DMODEL];
__device__ float g_v  [NTOK*DMODEL];
__device__ float g_z  [NTOK*DMODEL];
__device__ float g_gm [NTOK*DMODEL];
__device__ float g_t1 [NTOK*128];
__device__ float g_h  [NTOK*DMODEL];
__device__ float g_att[NTOK*DMODEL];
__device__ float g_ao [NTOK*DMODEL];
__device__ float g_y  [NTOK*DMODEL];
__device__ float g_yn [NTOK*DMODEL];
__device__ float g_f1 [NTOK*FFDIM];
__device__ unsigned g_bar_count;
__device__ unsigned g_bar_sense;

// ---------------- helpers ----------------
__device__ __forceinline__ void mma_tf32(float* c,
    unsigned a0, unsigned a1, unsigned a2, unsigned a3,
    unsigned b0, unsigned b1)
{
    asm volatile("mma.sync.aligned.m16n8k8.row.col.f32.tf32.tf32.f32 "
                 "{%0,%1,%2,%3}, {%4,%5,%6,%7}, {%8,%9}, {%0,%1,%2,%3};\n"
                 : "+f"(c[0]), "+f"(c[1]), "+f"(c[2]), "+f"(c[3])
                 : "r"(a0), "r"(a1), "r"(a2), "r"(a3), "r"(b0), "r"(b1));
}

__device__ __forceinline__ void cp_async16(uint32_t dst_smem, const void* src) {
    asm volatile("cp.async.cg.shared.global [%0], [%1], 16;"
                 :: "r"(dst_smem), "l"(src));
}
__device__ __forceinline__ void cp_commit() {
    asm volatile("cp.async.commit_group;");
}

__device__ __forceinline__ float multi_reduce32(float (&acc)[32], int lane) {
#pragma unroll
    for (int d = 16; d >= 1; d >>= 1) {
        const bool up = (lane & d) != 0;
#pragma unroll
        for (int i = 0; i < d; i++) {
            float send = up ? acc[i] : acc[i + d];
            float recv = __shfl_xor_sync(0xffffffffu, send, d);
            float keep = up ? acc[i + d] : acc[i];
            acc[i] = keep + recv;
        }
    }
    return acc[0];
}

__device__ __forceinline__ float block_sum256(float v) {
    __shared__ float sred[9];
#pragma unroll
    for (int o = 16; o; o >>= 1) v += __shfl_xor_sync(0xffffffffu, v, o);
    int w = threadIdx.x >> 5, l = threadIdx.x & 31;
    if (l == 0) sred[w] = v;
    __syncthreads();
    if (threadIdx.x < 32) {
        float t = (l < 8) ? sred[l] : 0.f;
#pragma unroll
        for (int o = 4; o; o >>= 1) t += __shfl_xor_sync(0xffffffffu, t, o);
        if (l == 0) sred[8] = t;
    }
    __syncthreads();
    return sred[8];
}

__global__ __launch_bounds__(256)
void rmsnorm_kernel(const float* __restrict__ x, const float* __restrict__ w,
                    float* __restrict__ out) {
    const size_t base = (size_t)blockIdx.x * DMODEL;
    float vb[4]; float ss = 0.f;
#pragma unroll
    for (int i = 0; i < 4; i++) { float t = x[base + threadIdx.x + 256*i]; vb[i] = t; ss += t*t; }
    float inv = 1.f / (sqrtf(block_sum256(ss)) * 0.03125f + 1e-6f);
#pragma unroll
    for (int i = 0; i < 4; i++) { int c = threadIdx.x + 256*i; out[base + c] = w[c] * vb[i] * inv; }
}

__global__ __launch_bounds__(256)
void residual_norm_kernel(const float* __restrict__ x, const float* __restrict__ ao,
                          const float* __restrict__ hs, const float* __restrict__ w,
                          float* __restrict__ y, float* __restrict__ yn) {
    const size_t base = (size_t)blockIdx.x * DMODEL;
    float vb[4]; float ss = 0.f;
#pragma unroll
    for (int i = 0; i < 4; i++) {
        int c = threadIdx.x + 256*i;
        float t = x[base+c] + ao[base+c] + hs[base+c];
        vb[i] = t; y[base+c] = t; ss += t*t;
    }
    float inv = 1.f / (sqrtf(block_sum256(ss)) * 0.03125f + 1e-6f);
#pragma unroll
    for (int i = 0; i < 4; i++) { int c = threadIdx.x + 256*i; yn[base+c] = w[c] * vb[i] * inv; }
}

// ---------------- TF32 tensor-core GEMM (cp.async, raw-f32 truncation) -------
// C[M,N] = A[M,K] @ B[N,K]^T + bias. Block 128x128, BK=16.
// SMEM layout [row][k], row stride 20 floats (conflict-free for frag LDS + 16B stores).
#define TG_BK 16
#define TG_RS 20

template<int EPI>
__device__ __forceinline__
void tgemm_body(const float* __restrict__ A, const float* __restrict__ B,
                const float* __restrict__ bias, const float* __restrict__ res,
                float* __restrict__ C, int N, int K,
                float (*As)[128][TG_RS], float (*Bs)[128][TG_RS],
                int bm, int bn)
{
    const int tid = threadIdx.x;
    const int wid = tid >> 5, lane = tid & 31;
    const int gq = lane >> 2, tq = lane & 3;
    const int m0 = (wid & 1) * 64, n0 = (wid >> 1) * 32;

    // cp.async mapping: thread -> row tid>>1, 8 consecutive k floats at (tid&1)*8
    const int crow = tid >> 1;
    const int ck  = (tid & 1) * 8;
    const float* Ap = A + (size_t)(bm + crow) * K + ck;
    const float* Bp = B + (size_t)(bn + crow) * K + ck;
    uint32_t dA0 = (uint32_t)__cvta_generic_to_shared(&As[0][crow][ck]);
    uint32_t dB0 = (uint32_t)__cvta_generic_to_shared(&Bs[0][crow][ck]);
    uint32_t dA1 = (uint32_t)__cvta_generic_to_shared(&As[1][crow][ck]);
    uint32_t dB1 = (uint32_t)__cvta_generic_to_shared(&Bs[1][crow][ck]);

    float acc[4][4][4];
#pragma unroll
    for (int i = 0; i < 4; i++)
#pragma unroll
        for (int j = 0; j < 4; j++)
#pragma unroll
            for (int e = 0; e < 4; e++) acc[i][j][e] = 0.f;

    // prologue: tile 0 into buf 0
    cp_async16(dA0,      Ap);
    cp_async16(dA0 + 16, Ap + 4);
    cp_async16(dB0,      Bp);
    cp_async16(dB0 + 16, Bp + 4);
    cp_commit();

    int buf = 0;
    for (int kt = 0; kt < K; kt += TG_BK) {
        const bool more = (kt + TG_BK) < K;
        if (more) {
            uint32_t da = buf ? dA0 : dA1;
            uint32_t db = buf ? dB0 : dB1;
            cp_async16(da,      Ap + kt + TG_BK);
            cp_async16(da + 16, Ap + kt + TG_BK + 4);
            cp_async16(db,      Bp + kt + TG_BK);
            cp_async16(db + 16, Bp + kt + TG_BK + 4);
            cp_commit();
            asm volatile("cp.async.wait_group 1;");
        } else {
            asm volatile("cp.async.wait_group 0;");
        }
        __syncthreads();
#pragma unroll
        for (int kb = 0; kb < TG_BK; kb += 8) {
            unsigned bf[4][2];
#pragma unroll
            for (int j = 0; j < 4; j++) {
                const int n = n0 + j*8 + gq;
                bf[j][0] = __float_as_uint(Bs[buf][n][kb+tq]);
                bf[j][1] = __float_as_uint(Bs[buf][n][kb+tq+4]);
            }
#pragma unroll
            for (int i = 0; i < 4; i++) {
                const int r = m0 + i*16 + gq;
                unsigned a0 = __float_as_uint(As[buf][r  ][kb+tq]);
                unsigned a1 = __float_as_uint(As[buf][r+8][kb+tq]);
                unsigned a2 = __float_as_uint(As[buf][r  ][kb+tq+4]);
                unsigned a3 = __float_as_uint(As[buf][r+8][kb+tq+4]);
#pragma unroll
                for (int j = 0; j < 4; j++)
                    mma_tf32(acc[i][j], a0, a1, a2, a3, bf[j][0], bf[j][1]);
            }
        }
        __syncthreads();   // all reads of buf done before it is refilled next iter
        buf ^= 1;
    }

#pragma unroll
    for (int i = 0; i < 4; i++) {
#pragma unroll
        for (int half = 0; half < 2; half++) {
            const int gr = bm + m0 + i*16 + gq + half*8;
            float* crowp = C + (size_t)gr * N;
            const float* rrow = res ? res + (size_t)gr * N : nullptr;
#pragma unroll
            for (int j = 0; j < 4; j++) {
                const int gc = bn + n0 + j*8 + tq*2;
#pragma unroll
                for (int e = 0; e < 2; e++) {
                    float vv = acc[i][j][half*2 + e] + bias[gc + e];
                    if (EPI == 1) vv = fmaxf(vv, 0.f);
                    else if (EPI == 2) {
                        vv = 1.f / (1.f + __expf(-vv));
                        vv = fminf(fmaxf(vv, 1e-6f), 1.f - 1e-6f);
                    } else if (EPI == 3) {
                        float u = 0.7978845608028654f * (vv + 0.044715f * vv * vv * vv);
                        vv = 0.5f * vv * (1.f + tanhf(u));
                    }
                    if (rrow) vv += rrow[gc + e];
                    crowp[gc + e] = vv;
                }
            }
        }
    }
}

template<int EPI>
__global__ __launch_bounds__(256, 2)
void tgemm_kernel(const float* __restrict__ A, const float* __restrict__ B,
                  const float* __restrict__ bias, const float* __restrict__ res,
                  float* __restrict__ C, int M, int N, int K)
{
    __shared__ float As[2][128][TG_RS];
    __shared__ float Bs[2][128][TG_RS];
    tgemm_body<EPI>(A, B, bias, res, C, N, K, As, Bs,
                    blockIdx.y * 128, blockIdx.x * 128);
}

struct Ptr3 { const float* B; const float* bias; float* C; };
struct Quad { Ptr3 p[4]; };

__global__ __launch_bounds__(256, 2)
void tgemm4_kernel(const float* __restrict__ A, Quad q, int N, int K)
{
    __shared__ float As[2][128][TG_RS];
    __shared__ float Bs[2][128][TG_RS];
    Ptr3 pr = q.p[blockIdx.z];
    tgemm_body<0>(A, pr.B, pr.bias, nullptr, pr.C, N, K, As, Bs,
                  blockIdx.y * 128, blockIdx.x * 128);
}

// ---------------- persistent recurrence (known-good) ----------------
__global__ __launch_bounds__(256, 1)
void recurrence_kernel(const float* __restrict__ z, const float* __restrict__ gm,
                       const float* __restrict__ Wg, const float* __restrict__ bg,
                       float* __restrict__ hs)
{
    const int tid = threadIdx.x, w = tid >> 5, l = tid & 31;
    const int blk = blockIdx.x;
    const int k0 = w * 128 + l * 4;
    float4 wv[8];
#pragma unroll
    for (int r = 0; r < 8; r++)
        wv[r] = *(const float4*)(Wg + (size_t)(blk*8 + r) * DMODEL + k0);

    __shared__ float red[256];
    float bgv = 0.f, hprev = 0.f; int jout = 0, bout = 0;
    if (tid < 32) { jout = blk*8 + (tid >> 2); bout = tid & 3; bgv = bg[jout]; }

    for (int t = 0; t < SEQ; t++) {
        float acc[32];
#pragma unroll
        for (int a = 0; a < 32; a++) acc[a] = 0.f;
        if (t > 0) {
#pragma unroll
            for (int b = 0; b < 4; b++) {
                float4 hv = __ldcg((const float4*)(hs + ((size_t)b*SEQ + (t-1))*DMODEL + k0));
#pragma unroll
                for (int r = 0; r < 8; r++) {
                    acc[r*4+b] = fmaf(wv[r].x, hv.x, acc[r*4+b]);
                    acc[r*4+b] = fmaf(wv[r].y, hv.y, acc[r*4+b]);
                    acc[r*4+b] = fmaf(wv[r].z, hv.z, acc[r*4+b]);
                    acc[r*4+b] = fmaf(wv[r].w, hv.w, acc[r*4+b]);
                }
            }
        }
        float part = multi_reduce32(acc, l);
        red[w*32 + l] = part;
        __syncthreads();
        if (tid < 32) {
            float sum = bgv;
#pragma unroll
            for (int ww = 0; ww < 8; ww++) sum += red[ww*32 + tid];
            float sig = 1.f / (1.f + __expf(-sum));
            size_t base = ((size_t)bout * SEQ + t) * DMODEL + jout;
            hprev = z[base] * sig + gm[base] * hprev;
            hs[base] = hprev;
            __threadfence();
        }
        __syncthreads();
        if (tid == 0) {
            unsigned sv = *(volatile unsigned*)&g_bar_sense;
            unsigned prev = atomicAdd(&g_bar_count, 1u);
            if (prev == REC_CTAS - 1) {
                g_bar_count = 0;
                __threadfence();
                atomicExch(&g_bar_sense, sv ^ 1u);
            } else {
                while (*(volatile unsigned*)&g_bar_sense == sv) { }
            }
            __threadfence();
        }
        __syncthreads();
    }
}

// ---------------- fused attention (butterfly PV; vectorized tile loads) -------
__global__ __launch_bounds__(256)
void attn_kernel(const float* __restrict__ q, const float* __restrict__ k,
                 const float* __restrict__ v, float* __restrict__ ao)
{
    const int qb = blockIdx.x & 127;
    const int bh = blockIdx.x >> 7;
    const int b = bh >> 4, h = bh & 15;
    __shared__ float Qs[8][64];
    __shared__ float Ts[64*65];
    const int tid = threadIdx.x, w = tid >> 5, l = tid & 31;
    const size_t bbase = (size_t)b * SEQ * DMODEL + (size_t)h * 64;
    const int qrow0 = qb * 8;

    if (tid < 128) {   // 8*64/4 = 128 float4 loads
        int r = tid >> 4, c4 = (tid & 15) * 4;
        float4 t = *(const float4*)(q + bbase + (size_t)(qrow0 + r) * DMODEL + c4);
        Qs[r][c4] = t.x; Qs[r][c4+1] = t.y; Qs[r][c4+2] = t.z; Qs[r][c4+3] = t.w;
    }

    float p[32];
#pragma unroll 1
    for (int j = 0; j < 16; j++) {
        __syncthreads();
#pragma unroll
        for (int it = 0; it < 4; it++) {   // 64*64/4 = 1024 float4 / 256 thr
            int idx = tid + it * 256;
            int r = idx >> 4, c4 = (idx & 15) * 4;
            float4 t = *(const float4*)(k + bbase + (size_t)(j*64 + r) * DMODEL + c4);
            float* dst = &Ts[r*65 + c4];
            dst[0]=t.x; dst[1]=t.y; dst[2]=t.z; dst[3]=t.w;
        }
        __syncthreads();
#pragma unroll
        for (int ii = 0; ii < 2; ii++) {
            const int kr = l + 32*ii;
            float s = 0.f;
#pragma unroll
            for (int d = 0; d < 64; d++) s = fmaf(Qs[w][d], Ts[kr*65 + d], s);
            p[2*j + ii] = s * 0.125f;
        }
    }
    float m = -3.0e38f;
#pragma unroll
    for (int i = 0; i < 32; i++) m = fmaxf(m, p[i]);
#pragma unroll
    for (int o = 16; o; o >>= 1) m = fmaxf(m, __shfl_xor_sync(0xffffffffu, m, o));
    float s = 0.f;
#pragma unroll
    for (int i = 0; i < 32; i++) { p[i] = __expf(p[i] - m); s += p[i]; }
#pragma unroll
    for (int o = 16; o; o >>= 1) s += __shfl_xor_sync(0xffffffffu, s, o);
    float inv = 1.f / s;
#pragma unroll
    for (int i = 0; i < 32; i++) p[i] *= inv;

    float o0[32], o1[32];
#pragma unroll
    for (int i = 0; i < 32; i++) { o0[i] = 0.f; o1[i] = 0.f; }
#pragma unroll 1
    for (int j = 0; j < 16; j++) {
        __syncthreads();
#pragma unroll
        for (int it = 0; it < 4; it++) {
            int idx = tid + it * 256;
            int r = idx >> 4, c4 = (idx & 15) * 4;
            float4 t = *(const float4*)(v + bbase + (size_t)(j*64 + r) * DMODEL + c4);
            float* dst = &Ts[r*65 + c4];
            dst[0]=t.x; dst[1]=t.y; dst[2]=t.z; dst[3]=t.w;
        }
        __syncthreads();
#pragma unroll
        for (int ii = 0; ii < 2; ii++) {
            const int kr = l + 32*ii;
            const float pi = p[2*j + ii];
#pragma unroll
            for (int d = 0; d < 32; d++) o0[d] = fmaf(pi, Ts[kr*65 + d],      o0[d]);
#pragma unroll
            for (int d = 0; d < 32; d++) o1[d] = fmaf(pi, Ts[kr*65 + 32 + d], o1[d]);
        }
    }
    float r0 = multi_reduce32(o0, l);
    float r1 = multi_reduce32(o1, l);
    size_t ob = bbase + (size_t)(qrow0 + w) * DMODEL;
    ao[ob + l] = r0;
    ao[ob + 32 + l] = r1;
}

extern "C" void kernel_launch(void* const* d_in, const int* in_sizes, int n_in,
                              void* d_out, int out_size)
{
    (void)in_sizes; (void)n_in; (void)out_size;
    const float* x   = (const float*)d_in[0];
    const float* n1w = (const float*)d_in[1];
    const float* Wq  = (const float*)d_in[2];  const float* bq = (const float*)d_in[3];
    const float* Wk  = (const float*)d_in[4];  const float* bk = (const float*)d_in[5];
    const float* Wv  = (const float*)d_in[6];  const float* bv = (const float*)d_in[7];
    const float* Wz  = (const float*)d_in[8];  const float* bz = (const float*)d_in[9];
    const float* Wg  = (const float*)d_in[10]; const float* bg = (const float*)d_in[11];
    const float* gdw = (const float*)d_in[12]; const float* gdb= (const float*)d_in[13];
    const float* guw = (const float*)d_in[14]; const float* gub= (const float*)d_in[15];
    const float* Wo  = (const float*)d_in[16]; const float* bo = (const float*)d_in[17];
    const float* n2w = (const float*)d_in[18];
    const float* f1w = (const float*)d_in[19]; const float* f1b= (const float*)d_in[20];
    const float* f2w = (const float*)d_in[21]; const float* f2b= (const float*)d_in[22];
    float* out = (float*)d_out;

    float *xn, *qp, *kp, *vp, *zp, *gmp, *t1, *hp, *attp, *aop, *yp, *ynp, *f1p;
    cudaGetSymbolAddress((void**)&xn,  g_xn);
    cudaGetSymbolAddress((void**)&qp,  g_q);
    cudaGetSymbolAddress((void**)&kp,  g_k);
    cudaGetSymbolAddress((void**)&vp,  g_v);
    cudaGetSymbolAddress((void**)&zp,  g_z);
    cudaGetSymbolAddress((void**)&gmp, g_gm);
    cudaGetSymbolAddress((void**)&t1,  g_t1);
    cudaGetSymbolAddress((void**)&hp,  g_h);
    cudaGetSymbolAddress((void**)&attp,g_att);
    cudaGetSymbolAddress((void**)&aop, g_ao);
    cudaGetSymbolAddress((void**)&yp,  g_y);
    cudaGetSymbolAddress((void**)&ynp, g_yn);
    cudaGetSymbolAddress((void**)&f1p, g_f1);

    // 1. rmsnorm
    rmsnorm_kernel<<<NTOK, 256>>>(x, n1w, xn);
    // 2. Q/K/V/Z projections fused into one launch
    Quad quad;
    quad.p[0] = {Wq, bq, qp};
    quad.p[1] = {Wk, bk, kp};
    quad.p[2] = {Wv, bv, vp};
    quad.p[3] = {Wz, bz, zp};
    tgemm4_kernel<<<dim3(DMODEL/128, NTOK/128, 4), 256>>>(xn, quad, DMODEL, DMODEL);
    // 3. gamma MLP
    tgemm_kernel<1><<<dim3(1, NTOK/128), 256>>>(zp, gdw, gdb, nullptr, t1, NTOK, 128, DMODEL);
    tgemm_kernel<2><<<dim3(DMODEL/128, NTOK/128), 256>>>(t1, guw, gub, nullptr, gmp, NTOK, DMODEL, 128);
    // 4. recurrence
    recurrence_kernel<<<REC_CTAS, 256>>>(zp, gmp, Wg, bg, hp);
    // 5. attention + Wo
    attn_kernel<<<4*16*128, 256>>>(qp, kp, vp, attp);
    tgemm_kernel<0><<<dim3(DMODEL/128, NTOK/128), 256>>>(attp, Wo, bo, nullptr, aop, NTOK, DMODEL, DMODEL);
    // 6-7. residual + norm2, FFN, final residual (-> d_out)
    residual_norm_kernel<<<NTOK, 256>>>(x, aop, hp, n2w, yp, ynp);
    tgemm_kernel<3><<<dim3(FFDIM/128, NTOK/128), 256>>>(ynp, f1w, f1b, nullptr, f1p, NTOK, FFDIM, DMODEL);
    tgemm_kernel<0><<<dim3(DMODEL/128, NTOK/128), 256>>>(f1p, f2w, f2b, yp, out, NTOK, DMODEL, FFDIM);
}

// round 11
// speedup vs baseline: 1.7810x; 1.0009x over previous
#include <cuda_runtime.h>
#include <cstddef>
#include <cstdint>
#include <math.h>

#define DMODEL 1024
#define NTOK   4096
#define FFDIM  4096
#define SEQ    1024
#define REC_CTAS 128

__device__ float g_xn [NTOK*DMODEL];
__device__ float g_q  [NTOK*DMODEL];
__device__ float g_k  [NTOK*DMODEL];
__device__ float g_v  [NTOK*DMODEL];
__device__ float g_z  [NTOK*DMODEL];
__device__ float g_gm [NTOK*DMODEL];
__device__ float g_t1 [NTOK*128];
__device__ float g_h  [NTOK*DMODEL];
__device__ float g_att[NTOK*DMODEL];
__device__ float g_ao [NTOK*DMODEL];
__device__ float g_y  [NTOK*DMODEL];
__device__ float g_yn [NTOK*DMODEL];
__device__ float g_f1 [NTOK*FFDIM];
__device__ unsigned g_bar_count;
__device__ unsigned g_bar_sense;

// ---------------- helpers ----------------
__device__ __forceinline__ void mma_tf32(float* c,
    unsigned a0, unsigned a1, unsigned a2, unsigned a3,
    unsigned b0, unsigned b1)
{
    asm volatile("mma.sync.aligned.m16n8k8.row.col.f32.tf32.tf32.f32 "
                 "{%0,%1,%2,%3}, {%4,%5,%6,%7}, {%8,%9}, {%0,%1,%2,%3};\n"
                 : "+f"(c[0]), "+f"(c[1]), "+f"(c[2]), "+f"(c[3])
                 : "r"(a0), "r"(a1), "r"(a2), "r"(a3), "r"(b0), "r"(b1));
}

__device__ __forceinline__ void cp_async16(uint32_t dst_smem, const void* src) {
    asm volatile("cp.async.cg.shared.global [%0], [%1], 16;"
                 :: "r"(dst_smem), "l"(src));
}
__device__ __forceinline__ void cp_commit() {
    asm volatile("cp.async.commit_group;");
}

__device__ __forceinline__ float multi_reduce32(float (&acc)[32], int lane) {
#pragma unroll
    for (int d = 16; d >= 1; d >>= 1) {
        const bool up = (lane & d) != 0;
#pragma unroll
        for (int i = 0; i < d; i++) {
            float send = up ? acc[i] : acc[i + d];
            float recv = __shfl_xor_sync(0xffffffffu, send, d);
            float keep = up ? acc[i + d] : acc[i];
            acc[i] = keep + recv;
        }
    }
    return acc[0];
}

__device__ __forceinline__ float block_sum256(float v) {
    __shared__ float sred[9];
#pragma unroll
    for (int o = 16; o; o >>= 1) v += __shfl_xor_sync(0xffffffffu, v, o);
    int w = threadIdx.x >> 5, l = threadIdx.x & 31;
    if (l == 0) sred[w] = v;
    __syncthreads();
    if (threadIdx.x < 32) {
        float t = (l < 8) ? sred[l] : 0.f;
#pragma unroll
        for (int o = 4; o; o >>= 1) t += __shfl_xor_sync(0xffffffffu, t, o);
        if (l == 0) sred[8] = t;
    }
    __syncthreads();
    return sred[8];
}

__global__ __launch_bounds__(256)
void rmsnorm_kernel(const float* __restrict__ x, const float* __restrict__ w,
                    float* __restrict__ out) {
    const size_t base = (size_t)blockIdx.x * DMODEL;
    float vb[4]; float ss = 0.f;
#pragma unroll
    for (int i = 0; i < 4; i++) { float t = x[base + threadIdx.x + 256*i]; vb[i] = t; ss += t*t; }
    float inv = 1.f / (sqrtf(block_sum256(ss)) * 0.03125f + 1e-6f);
#pragma unroll
    for (int i = 0; i < 4; i++) { int c = threadIdx.x + 256*i; out[base + c] = w[c] * vb[i] * inv; }
}

__global__ __launch_bounds__(256)
void residual_norm_kernel(const float* __restrict__ x, const float* __restrict__ ao,
                          const float* __restrict__ hs, const float* __restrict__ w,
                          float* __restrict__ y, float* __restrict__ yn) {
    const size_t base = (size_t)blockIdx.x * DMODEL;
    float vb[4]; float ss = 0.f;
#pragma unroll
    for (int i = 0; i < 4; i++) {
        int c = threadIdx.x + 256*i;
        float t = x[base+c] + ao[base+c] + hs[base+c];
        vb[i] = t; y[base+c] = t; ss += t*t;
    }
    float inv = 1.f / (sqrtf(block_sum256(ss)) * 0.03125f + 1e-6f);
#pragma unroll
    for (int i = 0; i < 4; i++) { int c = threadIdx.x + 256*i; yn[base+c] = w[c] * vb[i] * inv; }
}

// ---------------- TF32 tensor-core GEMM (3-stage cp.async ring) ---------------
// C[M,N] = A[M,K] @ B[N,K]^T + bias. Block 128x128, BK=16, one sync per tile.
#define TG_BK 16
#define TG_RS 20
#define TG_STAGE (128*TG_RS)        // floats per stage per operand
#define TG_SMEM_BYTES (2*3*TG_STAGE*4)

template<int EPI>
__device__ __forceinline__
void tgemm_body(const float* __restrict__ A, const float* __restrict__ B,
                const float* __restrict__ bias, const float* __restrict__ res,
                float* __restrict__ C, int N, int K,
                float* As, float* Bs, int bm, int bn)
{
    const int tid = threadIdx.x;
    const int wid = tid >> 5, lane = tid & 31;
    const int gq = lane >> 2, tq = lane & 3;
    const int m0 = (wid & 1) * 64, n0 = (wid >> 1) * 32;

    const int crow = tid >> 1;
    const int ck  = (tid & 1) * 8;
    const float* Ap = A + (size_t)(bm + crow) * K + ck;
    const float* Bp = B + (size_t)(bn + crow) * K + ck;

    uint32_t aSt[3], bSt[3];
#pragma unroll
    for (int st = 0; st < 3; st++) {
        aSt[st] = (uint32_t)__cvta_generic_to_shared(&As[st*TG_STAGE + crow*TG_RS + ck]);
        bSt[st] = (uint32_t)__cvta_generic_to_shared(&Bs[st*TG_STAGE + crow*TG_RS + ck]);
    }

    float acc[4][4][4];
#pragma unroll
    for (int i = 0; i < 4; i++)
#pragma unroll
        for (int j = 0; j < 4; j++)
#pragma unroll
            for (int e = 0; e < 4; e++) acc[i][j][e] = 0.f;

    // prologue: tiles 0,1 into stages 0,1 (one commit group each)
    cp_async16(aSt[0],      Ap);     cp_async16(aSt[0] + 16, Ap + 4);
    cp_async16(bSt[0],      Bp);     cp_async16(bSt[0] + 16, Bp + 4);
    cp_commit();
    if (TG_BK < K) {
        cp_async16(aSt[1],      Ap + TG_BK);     cp_async16(aSt[1] + 16, Ap + TG_BK + 4);
        cp_async16(bSt[1],      Bp + TG_BK);     cp_async16(bSt[1] + 16, Bp + TG_BK + 4);
    }
    cp_commit();

    int s = 0, s2 = 2;
    for (int kt = 0; kt < K; kt += TG_BK) {
        asm volatile("cp.async.wait_group 1;");   // tile for stage s resident
        __syncthreads();                          // also: all warps done with stage s2
        if (kt + 2*TG_BK < K) {
            const float* An = Ap + kt + 2*TG_BK;
            const float* Bn = Bp + kt + 2*TG_BK;
            cp_async16(aSt[s2],      An);     cp_async16(aSt[s2] + 16, An + 4);
            cp_async16(bSt[s2],      Bn);     cp_async16(bSt[s2] + 16, Bn + 4);
        }
        cp_commit();                              // always commit (exact group count)

        const float* Asb = As + s*TG_STAGE;
        const float* Bsb = Bs + s*TG_STAGE;
#pragma unroll
        for (int kb = 0; kb < TG_BK; kb += 8) {
            unsigned bf[4][2];
#pragma unroll
            for (int j = 0; j < 4; j++) {
                const int n = n0 + j*8 + gq;
                bf[j][0] = __float_as_uint(Bsb[n*TG_RS + kb+tq]);
                bf[j][1] = __float_as_uint(Bsb[n*TG_RS + kb+tq+4]);
            }
#pragma unroll
            for (int i = 0; i < 4; i++) {
                const int r = m0 + i*16 + gq;
                unsigned a0 = __float_as_uint(Asb[(r  )*TG_RS + kb+tq]);
                unsigned a1 = __float_as_uint(Asb[(r+8)*TG_RS + kb+tq]);
                unsigned a2 = __float_as_uint(Asb[(r  )*TG_RS + kb+tq+4]);
                unsigned a3 = __float_as_uint(Asb[(r+8)*TG_RS + kb+tq+4]);
#pragma unroll
                for (int j = 0; j < 4; j++)
                    mma_tf32(acc[i][j], a0, a1, a2, a3, bf[j][0], bf[j][1]);
            }
        }
        s  = (s  == 2) ? 0 : s  + 1;
        s2 = (s2 == 2) ? 0 : s2 + 1;
    }

#pragma unroll
    for (int i = 0; i < 4; i++) {
#pragma unroll
        for (int half = 0; half < 2; half++) {
            const int gr = bm + m0 + i*16 + gq + half*8;
            float* crowp = C + (size_t)gr * N;
            const float* rrow = res ? res + (size_t)gr * N : nullptr;
#pragma unroll
            for (int j = 0; j < 4; j++) {
                const int gc = bn + n0 + j*8 + tq*2;
#pragma unroll
                for (int e = 0; e < 2; e++) {
                    float vv = acc[i][j][half*2 + e] + bias[gc + e];
                    if (EPI == 1) vv = fmaxf(vv, 0.f);
                    else if (EPI == 2) {
                        vv = 1.f / (1.f + __expf(-vv));
                        vv = fminf(fmaxf(vv, 1e-6f), 1.f - 1e-6f);
                    } else if (EPI == 3) {
                        float u = 0.7978845608028654f * (vv + 0.044715f * vv * vv * vv);
                        vv = 0.5f * vv * (1.f + tanhf(u));
                    }
                    if (rrow) vv += rrow[gc + e];
                    crowp[gc + e] = vv;
                }
            }
        }
    }
}

template<int EPI>
__global__ __launch_bounds__(256, 2)
void tgemm_kernel(const float* __restrict__ A, const float* __restrict__ B,
                  const float* __restrict__ bias, const float* __restrict__ res,
                  float* __restrict__ C, int M, int N, int K)
{
    extern __shared__ float dsm[];
    tgemm_body<EPI>(A, B, bias, res, C, N, K, dsm, dsm + 3*TG_STAGE,
                    blockIdx.y * 128, blockIdx.x * 128);
}

struct Ptr3 { const float* B; const float* bias; float* C; };
struct Quad { Ptr3 p[4]; };

__global__ __launch_bounds__(256, 2)
void tgemm4_kernel(const float* __restrict__ A, Quad q, int N, int K)
{
    extern __shared__ float dsm[];
    Ptr3 pr = q.p[blockIdx.z];
    tgemm_body<0>(A, pr.B, pr.bias, nullptr, pr.C, N, K, dsm, dsm + 3*TG_STAGE,
                  blockIdx.y * 128, blockIdx.x * 128);
}

// ---------------- persistent recurrence (known-good) ----------------
__global__ __launch_bounds__(256, 1)
void recurrence_kernel(const float* __restrict__ z, const float* __restrict__ gm,
                       const float* __restrict__ Wg, const float* __restrict__ bg,
                       float* __restrict__ hs)
{
    const int tid = threadIdx.x, w = tid >> 5, l = tid & 31;
    const int blk = blockIdx.x;
    const int k0 = w * 128 + l * 4;
    float4 wv[8];
#pragma unroll
    for (int r = 0; r < 8; r++)
        wv[r] = *(const float4*)(Wg + (size_t)(blk*8 + r) * DMODEL + k0);

    __shared__ float red[256];
    float bgv = 0.f, hprev = 0.f; int jout = 0, bout = 0;
    if (tid < 32) { jout = blk*8 + (tid >> 2); bout = tid & 3; bgv = bg[jout]; }

    for (int t = 0; t < SEQ; t++) {
        float acc[32];
#pragma unroll
        for (int a = 0; a < 32; a++) acc[a] = 0.f;
        if (t > 0) {
#pragma unroll
            for (int b = 0; b < 4; b++) {
                float4 hv = __ldcg((const float4*)(hs + ((size_t)b*SEQ + (t-1))*DMODEL + k0));
#pragma unroll
                for (int r = 0; r < 8; r++) {
                    acc[r*4+b] = fmaf(wv[r].x, hv.x, acc[r*4+b]);
                    acc[r*4+b] = fmaf(wv[r].y, hv.y, acc[r*4+b]);
                    acc[r*4+b] = fmaf(wv[r].z, hv.z, acc[r*4+b]);
                    acc[r*4+b] = fmaf(wv[r].w, hv.w, acc[r*4+b]);
                }
            }
        }
        float part = multi_reduce32(acc, l);
        red[w*32 + l] = part;
        __syncthreads();
        if (tid < 32) {
            float sum = bgv;
#pragma unroll
            for (int ww = 0; ww < 8; ww++) sum += red[ww*32 + tid];
            float sig = 1.f / (1.f + __expf(-sum));
            size_t base = ((size_t)bout * SEQ + t) * DMODEL + jout;
            hprev = z[base] * sig + gm[base] * hprev;
            hs[base] = hprev;
            __threadfence();
        }
        __syncthreads();
        if (tid == 0) {
            unsigned sv = *(volatile unsigned*)&g_bar_sense;
            unsigned prev = atomicAdd(&g_bar_count, 1u);
            if (prev == REC_CTAS - 1) {
                g_bar_count = 0;
                __threadfence();
                atomicExch(&g_bar_sense, sv ^ 1u);
            } else {
                while (*(volatile unsigned*)&g_bar_sense == sv) { }
            }
            __threadfence();
        }
        __syncthreads();
    }
}

// ---------------- fused attention (butterfly PV + register prefetch) ----------
__global__ __launch_bounds__(256)
void attn_kernel(const float* __restrict__ q, const float* __restrict__ k,
                 const float* __restrict__ v, float* __restrict__ ao)
{
    const int qb = blockIdx.x & 127;
    const int bh = blockIdx.x >> 7;
    const int b = bh >> 4, h = bh & 15;
    __shared__ float Qs[8][64];
    __shared__ float Ts[64*65];
    const int tid = threadIdx.x, w = tid >> 5, l = tid & 31;
    const size_t bbase = (size_t)b * SEQ * DMODEL + (size_t)h * 64;
    const int qrow0 = qb * 8;

    const int pr_r  = tid >> 4;          // prefetch row base (0..15), +16 per chunk
    const int pr_c4 = (tid & 15) * 4;    // prefetch column (float4)

    if (tid < 128) {
        int r = tid >> 4, c4 = (tid & 15) * 4;
        float4 t = *(const float4*)(q + bbase + (size_t)(qrow0 + r) * DMODEL + c4);
        Qs[r][c4] = t.x; Qs[r][c4+1] = t.y; Qs[r][c4+2] = t.z; Qs[r][c4+3] = t.w;
    }

    float4 pf[4];
#pragma unroll
    for (int it = 0; it < 4; it++)
        pf[it] = *(const float4*)(k + bbase + (size_t)(pr_r + it*16) * DMODEL + pr_c4);

    float p[32];
#pragma unroll 1
    for (int j = 0; j < 16; j++) {
        __syncthreads();                 // previous tile's compute done -> Ts free
#pragma unroll
        for (int it = 0; it < 4; it++) {
            float* dst = &Ts[(pr_r + it*16)*65 + pr_c4];
            dst[0]=pf[it].x; dst[1]=pf[it].y; dst[2]=pf[it].z; dst[3]=pf[it].w;
        }
        __syncthreads();
        if (j < 15) {
#pragma unroll
            for (int it = 0; it < 4; it++)
                pf[it] = *(const float4*)(k + bbase + (size_t)((j+1)*64 + pr_r + it*16) * DMODEL + pr_c4);
        }
#pragma unroll
        for (int ii = 0; ii < 2; ii++) {
            const int kr = l + 32*ii;
            float s = 0.f;
#pragma unroll
            for (int d = 0; d < 64; d++) s = fmaf(Qs[w][d], Ts[kr*65 + d], s);
            p[2*j + ii] = s * 0.125f;
        }
    }

    // prefetch V tile 0 before softmax (hides latency under the reductions)
#pragma unroll
    for (int it = 0; it < 4; it++)
        pf[it] = *(const float4*)(v + bbase + (size_t)(pr_r + it*16) * DMODEL + pr_c4);

    float m = -3.0e38f;
#pragma unroll
    for (int i = 0; i < 32; i++) m = fmaxf(m, p[i]);
#pragma unroll
    for (int o = 16; o; o >>= 1) m = fmaxf(m, __shfl_xor_sync(0xffffffffu, m, o));
    float s = 0.f;
#pragma unroll
    for (int i = 0; i < 32; i++) { p[i] = __expf(p[i] - m); s += p[i]; }
#pragma unroll
    for (int o = 16; o; o >>= 1) s += __shfl_xor_sync(0xffffffffu, s, o);
    float inv = 1.f / s;
#pragma unroll
    for (int i = 0; i < 32; i++) p[i] *= inv;

    float o0[32], o1[32];
#pragma unroll
    for (int i = 0; i < 32; i++) { o0[i] = 0.f; o1[i] = 0.f; }
#pragma unroll 1
    for (int j = 0; j < 16; j++) {
        __syncthreads();
#pragma unroll
        for (int it = 0; it < 4; it++) {
            float* dst = &Ts[(pr_r + it*16)*65 + pr_c4];
            dst[0]=pf[it].x; dst[1]=pf[it].y; dst[2]=pf[it].z; dst[3]=pf[it].w;
        }
        __syncthreads();
        if (j < 15) {
#pragma unroll
            for (int it = 0; it < 4; it++)
                pf[it] = *(const float4*)(v + bbase + (size_t)((j+1)*64 + pr_r + it*16) * DMODEL + pr_c4);
        }
#pragma unroll
        for (int ii = 0; ii < 2; ii++) {
            const int kr = l + 32*ii;
            const float pi = p[2*j + ii];
#pragma unroll
            for (int d = 0; d < 32; d++) o0[d] = fmaf(pi, Ts[kr*65 + d],      o0[d]);
#pragma unroll
            for (int d = 0; d < 32; d++) o1[d] = fmaf(pi, Ts[kr*65 + 32 + d], o1[d]);
        }
    }
    float r0 = multi_reduce32(o0, l);
    float r1 = multi_reduce32(o1, l);
    size_t ob = bbase + (size_t)(qrow0 + w) * DMODEL;
    ao[ob + l] = r0;
    ao[ob + 32 + l] = r1;
}

extern "C" void kernel_launch(void* const* d_in, const int* in_sizes, int n_in,
                              void* d_out, int out_size)
{
    (void)in_sizes; (void)n_in; (void)out_size;
    const float* x   = (const float*)d_in[0];
    const float* n1w = (const float*)d_in[1];
    const float* Wq  = (const float*)d_in[2];  const float* bq = (const float*)d_in[3];
    const float* Wk  = (const float*)d_in[4];  const float* bk = (const float*)d_in[5];
    const float* Wv  = (const float*)d_in[6];  const float* bv = (const float*)d_in[7];
    const float* Wz  = (const float*)d_in[8];  const float* bz = (const float*)d_in[9];
    const float* Wg  = (const float*)d_in[10]; const float* bg = (const float*)d_in[11];
    const float* gdw = (const float*)d_in[12]; const float* gdb= (const float*)d_in[13];
    const float* guw = (const float*)d_in[14]; const float* gub= (const float*)d_in[15];
    const float* Wo  = (const float*)d_in[16]; const float* bo = (const float*)d_in[17];
    const float* n2w = (const float*)d_in[18];
    const float* f1w = (const float*)d_in[19]; const float* f1b= (const float*)d_in[20];
    const float* f2w = (const float*)d_in[21]; const float* f2b= (const float*)d_in[22];
    float* out = (float*)d_out;

    float *xn, *qp, *kp, *vp, *zp, *gmp, *t1, *hp, *attp, *aop, *yp, *ynp, *f1p;
    cudaGetSymbolAddress((void**)&xn,  g_xn);
    cudaGetSymbolAddress((void**)&qp,  g_q);
    cudaGetSymbolAddress((void**)&kp,  g_k);
    cudaGetSymbolAddress((void**)&vp,  g_v);
    cudaGetSymbolAddress((void**)&zp,  g_z);
    cudaGetSymbolAddress((void**)&gmp, g_gm);
    cudaGetSymbolAddress((void**)&t1,  g_t1);
    cudaGetSymbolAddress((void**)&hp,  g_h);
    cudaGetSymbolAddress((void**)&attp,g_att);
    cudaGetSymbolAddress((void**)&aop, g_ao);
    cudaGetSymbolAddress((void**)&yp,  g_y);
    cudaGetSymbolAddress((void**)&ynp, g_yn);
    cudaGetSymbolAddress((void**)&f1p, g_f1);

    // allow 61.4 KB dynamic smem on the GEMM kernels (idempotent, capture-safe)
    cudaFuncSetAttribute(tgemm_kernel<0>, cudaFuncAttributeMaxDynamicSharedMemorySize, TG_SMEM_BYTES);
    cudaFuncSetAttribute(tgemm_kernel<1>, cudaFuncAttributeMaxDynamicSharedMemorySize, TG_SMEM_BYTES);
    cudaFuncSetAttribute(tgemm_kernel<2>, cudaFuncAttributeMaxDynamicSharedMemorySize, TG_SMEM_BYTES);
    cudaFuncSetAttribute(tgemm_kernel<3>, cudaFuncAttributeMaxDynamicSharedMemorySize, TG_SMEM_BYTES);
    cudaFuncSetAttribute(tgemm4_kernel,   cudaFuncAttributeMaxDynamicSharedMemorySize, TG_SMEM_BYTES);

    // 1. rmsnorm
    rmsnorm_kernel<<<NTOK, 256>>>(x, n1w, xn);
    // 2. Q/K/V/Z projections fused into one launch
    Quad quad;
    quad.p[0] = {Wq, bq, qp};
    quad.p[1] = {Wk, bk, kp};
    quad.p[2] = {Wv, bv, vp};
    quad.p[3] = {Wz, bz, zp};
    tgemm4_kernel<<<dim3(DMODEL/128, NTOK/128, 4), 256, TG_SMEM_BYTES>>>(xn, quad, DMODEL, DMODEL);
    // 3. gamma MLP
    tgemm_kernel<1><<<dim3(1, NTOK/128), 256, TG_SMEM_BYTES>>>(zp, gdw, gdb, nullptr, t1, NTOK, 128, DMODEL);
    tgemm_kernel<2><<<dim3(DMODEL/128, NTOK/128), 256, TG_SMEM_BYTES>>>(t1, guw, gub, nullptr, gmp, NTOK, DMODEL, 128);
    // 4. recurrence
    recurrence_kernel<<<REC_CTAS, 256>>>(zp, gmp, Wg, bg, hp);
    // 5. attention + Wo
    attn_kernel<<<4*16*128, 256>>>(qp, kp, vp, attp);
    tgemm_kernel<0><<<dim3(DMODEL/128, NTOK/128), 256, TG_SMEM_BYTES>>>(attp, Wo, bo, nullptr, aop, NTOK, DMODEL, DMODEL);
    // 6-7. residual + norm2, FFN, final residual (-> d_out)
    residual_norm_kernel<<<NTOK, 256>>>(x, aop, hp, n2w, yp, ynp);
    tgemm_kernel<3><<<dim3(FFDIM/128, NTOK/128), 256, TG_SMEM_BYTES>>>(ynp, f1w, f1b, nullptr, f1p, NTOK, FFDIM, DMODEL);
    tgemm_kernel<0><<<dim3(DMODEL/128, NTOK/128), 256, TG_SMEM_BYTES>>>(f1p, f2w, f2b, yp, out, NTOK, DMODEL, FFDIM);
}